// round 14
// baseline (speedup 1.0000x reference)
#include <cuda_runtime.h>
#include <cuda_bf16.h>
#include <cstdint>

#define HD 128
#define WPB 8                       // warps per CTA
#define NTHREADS (WPB * 32)
#define GRID1 740                   // 148 SMs * 5 CTAs (regs<=48 -> 5 CTAs/SM resident)
#define NWTOT (GRID1 * WPB)         // 5920 worker warps
#define NCHUNK (NWTOT * 2)          // 2x oversubscription for work stealing
#define BMAX 2048                   // scratch sized for up to 2048 segments

// ---- persistent scratch (zero-initialized at module load) ----
// Bookkeeping is indexed by CHUNK id (0..NCHUNK-1): every chunk is grabbed by
// exactly one warp per run, so each slot has a unique writer -> deterministic
// output regardless of which warp grabs which chunk.
// Invariant: for an EMPTY segment s nothing ever writes g_seg_bounds[s] (any
// run, any replay) so it stays {0,0}; a NON-EMPTY segment gets .y = j >= 1
// from exactly one chunk. g_ticket is reset by K2 (strictly after K1) so
// every graph replay starts from 0.
__device__ float g_head_num[NCHUNK * HD];
__device__ float g_tail_num[NCHUNK * HD];
__device__ float g_head_d[NCHUNK];
__device__ float g_tail_d[NCHUNK];
__device__ int   g_head_seg[NCHUNK];
__device__ int   g_tail_seg[NCHUNK];
__device__ float g_num_acc[BMAX * HD];   // direct-stored exclusive segments
__device__ float g_d_acc[BMAX];
__device__ int2  g_seg_bounds[BMAX];     // .x = start row, .y = end row (0 => empty)
__device__ unsigned g_ticket;            // chunk work-stealing counter

// K1: warps grab contiguous row chunks [c*cs, min((c+1)*cs, N)) from a global
// ticket (2 chunks/warp on average) — dynamic assignment absorbs the ~10%
// inter-SM speed spread that a static partition pays in tail time. Per chunk:
// split into same-segment runs, accumulate d = sum exp(s_i) and
// num = sum exp(s_i)*x_i, flush to exclusive slot or chunk head/tail slot,
// record true segment bounds (unique writer per 4B word).
__global__ void __launch_bounds__(NTHREADS, 5)
gap_k1(const float* __restrict__ x,
       const int*   __restrict__ batch,
       const float* __restrict__ W,
       int N)
{
    const int lane = threadIdx.x & 31;
    const int cs   = (N + NCHUNK - 1) / NCHUNK;   // rows per chunk

    const float4 Wv = *reinterpret_cast<const float4*>(W + lane * 4);
    const long long col = (long long)lane * 4;

    // grab first chunk
    unsigned c;
    if (lane == 0) c = atomicAdd(&g_ticket, 1u);
    c = __shfl_sync(0xffffffffu, c, 0);

    while (c < NCHUNK) {
        // prefetch next ticket so the ATOMG round trip overlaps processing
        unsigned cn;
        if (lane == 0) cn = atomicAdd(&g_ticket, 1u);
        cn = __shfl_sync(0xffffffffu, cn, 0);

        const int lo = (int)(c * (unsigned)cs);
        const int hi = min(lo + cs, N);
        int hseg = -1, tseg = -1;

        if (lo < N) {
            int i = lo;
            while (i < hi) {
                const int seg = batch[i];
                // upper_bound(seg) in (i, hi)
                int a = i + 1, b = hi;
                while (a < b) { int m = (a + b) >> 1; if (batch[m] <= seg) a = m + 1; else b = m; }
                const int j = a;

                float  d = 0.0f;
                float4 num = make_float4(0.0f, 0.0f, 0.0f, 0.0f);

                int r = i;
                // 4 consecutive rows per iter: 4 independent LDG.128, 2KB contiguous
                for (; r + 4 <= j; r += 4) {
                    const float4 x0 = __ldcs(reinterpret_cast<const float4*>(x + (long long)(r    ) * HD + col));
                    const float4 x1 = __ldcs(reinterpret_cast<const float4*>(x + (long long)(r + 1) * HD + col));
                    const float4 x2 = __ldcs(reinterpret_cast<const float4*>(x + (long long)(r + 2) * HD + col));
                    const float4 x3 = __ldcs(reinterpret_cast<const float4*>(x + (long long)(r + 3) * HD + col));

                    float p0 = x0.x * Wv.x + x0.y * Wv.y + x0.z * Wv.z + x0.w * Wv.w;
                    float p1 = x1.x * Wv.x + x1.y * Wv.y + x1.z * Wv.z + x1.w * Wv.w;
                    float p2 = x2.x * Wv.x + x2.y * Wv.y + x2.z * Wv.z + x2.w * Wv.w;
                    float p3 = x3.x * Wv.x + x3.y * Wv.y + x3.z * Wv.z + x3.w * Wv.w;
                    #pragma unroll
                    for (int o = 16; o > 0; o >>= 1) {
                        p0 += __shfl_xor_sync(0xffffffffu, p0, o);
                        p1 += __shfl_xor_sync(0xffffffffu, p1, o);
                        p2 += __shfl_xor_sync(0xffffffffu, p2, o);
                        p3 += __shfl_xor_sync(0xffffffffu, p3, o);
                    }
                    const float e0 = __expf(p0);
                    const float e1 = __expf(p1);
                    const float e2 = __expf(p2);
                    const float e3 = __expf(p3);
                    d += (e0 + e1) + (e2 + e3);
                    num.x += e0 * x0.x + e1 * x1.x + e2 * x2.x + e3 * x3.x;
                    num.y += e0 * x0.y + e1 * x1.y + e2 * x2.y + e3 * x3.y;
                    num.z += e0 * x0.z + e1 * x1.z + e2 * x2.z + e3 * x3.z;
                    num.w += e0 * x0.w + e1 * x1.w + e2 * x2.w + e3 * x3.w;
                }
                for (; r < j; r++) {
                    const float4 xv = __ldcs(reinterpret_cast<const float4*>(x + (long long)r * HD + col));
                    float p = xv.x * Wv.x + xv.y * Wv.y + xv.z * Wv.z + xv.w * Wv.w;
                    #pragma unroll
                    for (int o = 16; o > 0; o >>= 1) p += __shfl_xor_sync(0xffffffffu, p, o);
                    const float e = __expf(p);
                    d += e;
                    num.x += e * xv.x; num.y += e * xv.y; num.z += e * xv.z; num.w += e * xv.w;
                }

                const bool sb = (i == lo) && (lo > 0) && (batch[lo - 1] == seg);   // continues before
                const bool ea = (j == hi) && (hi < N) && (batch[hi] == seg);       // continues after

                if (lane == 0) {
                    if (!sb) g_seg_bounds[seg].x = i;   // true segment start (unique writer)
                    if (!ea) g_seg_bounds[seg].y = j;   // true segment end   (unique writer, j >= 1)
                }

                if (!sb && !ea) {
                    // exclusive segment: this chunk is the sole contributor
                    *reinterpret_cast<float4*>(g_num_acc + (long long)seg * HD + lane * 4) = num;
                    if (lane == 0) g_d_acc[seg] = d;
                } else if (sb) {
                    hseg = seg;
                    *reinterpret_cast<float4*>(g_head_num + (long long)c * HD + lane * 4) = num;
                    if (lane == 0) g_head_d[c] = d;
                } else {
                    tseg = seg;
                    *reinterpret_cast<float4*>(g_tail_num + (long long)c * HD + lane * 4) = num;
                    if (lane == 0) g_tail_d[c] = d;
                }
                i = j;
            }
        }
        if (lane == 0) { g_head_seg[c] = hseg; g_tail_seg[c] = tseg; }

        c = cn;
    }
}

// K2: one WARP per segment (8 segments per 256-thread CTA, grid B/8).
// Lane l owns columns [4l, 4l+4) as a float4; scans the chunks overlapping
// the segment for head/tail partials (lane-uniform conditions, coalesced
// float4 scratch loads). Also resets the work-stealing ticket for the next
// replay (K2 runs strictly after K1 finishes all grabs).
// Empty segment: g_seg_bounds[s].y == 0 (never written; zero-init) -> zeros.
__global__ void __launch_bounds__(NTHREADS)
gap_k2(float* __restrict__ out, int N, int B)
{
    if (blockIdx.x == 0 && threadIdx.x == 0) g_ticket = 0;   // reset for next replay

    const int wid  = threadIdx.x >> 5;
    const int lane = threadIdx.x & 31;
    const int s    = blockIdx.x * WPB + wid;
    if (s >= B) return;

    float4* outv = reinterpret_cast<float4*>(out + (long long)s * HD + lane * 4);

    const int2 bounds = g_seg_bounds[s];          // one 8B load: {start, end}
    if (bounds.y == 0) { *outv = make_float4(0.0f, 0.0f, 0.0f, 0.0f); return; }

    const int cs  = (N + NCHUNK - 1) / NCHUNK;
    const int glo = bounds.x / cs;
    const int ghi = (bounds.y - 1) / cs;

    float4 num = make_float4(0.0f, 0.0f, 0.0f, 0.0f);
    float  d = 0.0f;
    int matches = 0;
    for (int g = glo; g <= ghi; g++) {
        if (g_head_seg[g] == s) {
            const float4 v = *reinterpret_cast<const float4*>(g_head_num + (long long)g * HD + lane * 4);
            num.x += v.x; num.y += v.y; num.z += v.z; num.w += v.w;
            d += g_head_d[g]; matches++;
        }
        if (g_tail_seg[g] == s) {
            const float4 v = *reinterpret_cast<const float4*>(g_tail_num + (long long)g * HD + lane * 4);
            num.x += v.x; num.y += v.y; num.z += v.z; num.w += v.w;
            d += g_tail_d[g]; matches++;
        }
    }
    if (matches == 0) {
        num = *reinterpret_cast<const float4*>(g_num_acc + (long long)s * HD + lane * 4);
        d   = g_d_acc[s];
    }
    const float inv = 1.0f / (d + 1e-16f);
    num.x *= inv; num.y *= inv; num.z *= inv; num.w *= inv;
    *outv = num;
}

extern "C" void kernel_launch(void* const* d_in, const int* in_sizes, int n_in,
                              void* d_out, int out_size)
{
    const float* x     = (const float*)d_in[0];
    // d_in[1] = edge_index (unused by the forward math)
    const int*   batch = (const int*)d_in[2];
    const float* W     = (const float*)d_in[3];
    // d_in[4] = b (zeros; cancels in the softmax)
    float* out = (float*)d_out;

    const int N = in_sizes[2];
    const int B = out_size / HD;

    gap_k1<<<GRID1, NTHREADS>>>(x, batch, W, N);
    gap_k2<<<(B + WPB - 1) / WPB, NTHREADS>>>(out, N, B);
}

// round 15
// speedup vs baseline: 1.1148x; 1.1148x over previous
#include <cuda_runtime.h>
#include <cuda_bf16.h>
#include <cstdint>

#define HD 128
#define WPB 8                       // warps per CTA
#define NTHREADS (WPB * 32)
#define GRID1 740                   // 148 SMs * 5 CTAs (regs<=48 -> 5 CTAs/SM resident)
#define NWTOT (GRID1 * WPB)         // 5920 worker warps
#define BMAX 2048                   // scratch sized for up to 2048 segments

// ---- persistent scratch (zero-initialized at module load) ----
// Invariant: for an EMPTY segment s nothing ever writes g_seg_end[s] (any run,
// any replay) so it stays 0; a NON-EMPTY segment gets g_seg_end[s]=j>=1 from
// exactly one warp. Hence g_seg_end[s]==0 <=> empty; no init kernel needed.
// All scratch values are always finite (zeros or finite exp-sums), which the
// predicated K2 relies on (0.0f * finite == 0.0f exactly).
__device__ float g_head_num[NWTOT * HD];
__device__ float g_tail_num[NWTOT * HD];
__device__ float g_head_d[NWTOT];
__device__ float g_tail_d[NWTOT];
__device__ int   g_head_seg[NWTOT];
__device__ int   g_tail_seg[NWTOT];
__device__ float g_num_acc[BMAX * HD];   // direct-stored exclusive segments
__device__ float g_d_acc[BMAX];
__device__ int   g_seg_start[BMAX];
__device__ int   g_seg_end[BMAX];        // 0 => empty segment

// K1 (identical to the 87.7us best): each global warp g owns contiguous rows
// [g*RPW, min((g+1)*RPW, N)). Splits its range into same-segment runs;
// accumulates d = sum exp(s_i), num = sum exp(s_i)*x_i per run; flushes each
// run to the exclusive per-segment slot or the warp's head/tail partial slot.
// Records TRUE segment start/end rows (single writer each).
__global__ void __launch_bounds__(NTHREADS, 5)
gap_k1(const float* __restrict__ x,
       const int*   __restrict__ batch,
       const float* __restrict__ W,
       int N)
{
    const int wid  = threadIdx.x >> 5;
    const int lane = threadIdx.x & 31;
    const int g    = blockIdx.x * WPB + wid;

    const int rpw = (N + NWTOT - 1) / NWTOT;
    const long long rl = (long long)g * rpw;

    int hseg = -1, tseg = -1;

    if (rl < N) {
        const int lo = (int)rl;
        const int hi = min(lo + rpw, N);
        const float4 Wv = *reinterpret_cast<const float4*>(W + lane * 4);
        const long long col = (long long)lane * 4;

        int i = lo;
        while (i < hi) {
            const int seg = batch[i];
            // upper_bound(seg) in (i, hi)
            int a = i + 1, b = hi;
            while (a < b) { int m = (a + b) >> 1; if (batch[m] <= seg) a = m + 1; else b = m; }
            const int j = a;

            float  d = 0.0f;
            float4 num = make_float4(0.0f, 0.0f, 0.0f, 0.0f);

            int r = i;
            // 4 consecutive rows per iter: 4 independent LDG.128, 2KB contiguous
            for (; r + 4 <= j; r += 4) {
                const float4 x0 = __ldcs(reinterpret_cast<const float4*>(x + (long long)(r    ) * HD + col));
                const float4 x1 = __ldcs(reinterpret_cast<const float4*>(x + (long long)(r + 1) * HD + col));
                const float4 x2 = __ldcs(reinterpret_cast<const float4*>(x + (long long)(r + 2) * HD + col));
                const float4 x3 = __ldcs(reinterpret_cast<const float4*>(x + (long long)(r + 3) * HD + col));

                float p0 = x0.x * Wv.x + x0.y * Wv.y + x0.z * Wv.z + x0.w * Wv.w;
                float p1 = x1.x * Wv.x + x1.y * Wv.y + x1.z * Wv.z + x1.w * Wv.w;
                float p2 = x2.x * Wv.x + x2.y * Wv.y + x2.z * Wv.z + x2.w * Wv.w;
                float p3 = x3.x * Wv.x + x3.y * Wv.y + x3.z * Wv.z + x3.w * Wv.w;
                #pragma unroll
                for (int o = 16; o > 0; o >>= 1) {
                    p0 += __shfl_xor_sync(0xffffffffu, p0, o);
                    p1 += __shfl_xor_sync(0xffffffffu, p1, o);
                    p2 += __shfl_xor_sync(0xffffffffu, p2, o);
                    p3 += __shfl_xor_sync(0xffffffffu, p3, o);
                }
                const float e0 = __expf(p0);
                const float e1 = __expf(p1);
                const float e2 = __expf(p2);
                const float e3 = __expf(p3);
                d += (e0 + e1) + (e2 + e3);
                num.x += e0 * x0.x + e1 * x1.x + e2 * x2.x + e3 * x3.x;
                num.y += e0 * x0.y + e1 * x1.y + e2 * x2.y + e3 * x3.y;
                num.z += e0 * x0.z + e1 * x1.z + e2 * x2.z + e3 * x3.z;
                num.w += e0 * x0.w + e1 * x1.w + e2 * x2.w + e3 * x3.w;
            }
            for (; r < j; r++) {
                const float4 xv = __ldcs(reinterpret_cast<const float4*>(x + (long long)r * HD + col));
                float p = xv.x * Wv.x + xv.y * Wv.y + xv.z * Wv.z + xv.w * Wv.w;
                #pragma unroll
                for (int o = 16; o > 0; o >>= 1) p += __shfl_xor_sync(0xffffffffu, p, o);
                const float e = __expf(p);
                d += e;
                num.x += e * xv.x; num.y += e * xv.y; num.z += e * xv.z; num.w += e * xv.w;
            }

            const bool sb = (i == lo) && (lo > 0) && (batch[lo - 1] == seg);   // continues before
            const bool ea = (j == hi) && (hi < N) && (batch[hi] == seg);       // continues after

            if (lane == 0) {
                if (!sb) g_seg_start[seg] = i;   // true segment start (unique writer)
                if (!ea) g_seg_end[seg]   = j;   // true segment end   (unique writer, j >= 1)
            }

            if (!sb && !ea) {
                // exclusive segment: this warp is the sole contributor
                *reinterpret_cast<float4*>(g_num_acc + (long long)seg * HD + lane * 4) = num;
                if (lane == 0) g_d_acc[seg] = d;
            } else if (sb) {
                hseg = seg;
                *reinterpret_cast<float4*>(g_head_num + (long long)g * HD + lane * 4) = num;
                if (lane == 0) g_head_d[g] = d;
            } else {
                tseg = seg;
                *reinterpret_cast<float4*>(g_tail_num + (long long)g * HD + lane * 4) = num;
                if (lane == 0) g_tail_d[g] = d;
            }
            i = j;
        }
    }
    if (lane == 0) { g_head_seg[g] = hseg; g_tail_seg[g] = tseg; }
}

// K2: one WARP per segment (8 segments per 256-thread CTA, grid B/8).
// BRANCH-FREE gather: every overlapping warp-slot's seg ids, d scalars and
// 512B num rows are loaded UNCONDITIONALLY and accumulated with a 0/1
// predicate factor. This removes the compare->branch->load dependent chain
// (~7 serialized L2 round trips) in favor of independent pipelined loads.
// Stale scratch rows are finite, and 0.0f * finite == 0.0f exactly, so the
// result is bitwise identical to the branchy version.
// Empty segment: g_seg_end[s] == 0 (never written; zero-init) -> zeros.
__global__ void __launch_bounds__(NTHREADS)
gap_k2(float* __restrict__ out, int N, int B)
{
    const int wid  = threadIdx.x >> 5;
    const int lane = threadIdx.x & 31;
    const int s    = blockIdx.x * WPB + wid;
    if (s >= B) return;

    float4* outv = reinterpret_cast<float4*>(out + (long long)s * HD + lane * 4);

    const int se = g_seg_end[s];
    if (se == 0) { *outv = make_float4(0.0f, 0.0f, 0.0f, 0.0f); return; }
    const int ss = g_seg_start[s];

    const int rpw = (N + NWTOT - 1) / NWTOT;
    const int glo = ss / rpw;
    const int ghi = (se - 1) / rpw;

    float4 num = make_float4(0.0f, 0.0f, 0.0f, 0.0f);
    float  d = 0.0f;
    int matches = 0;
    #pragma unroll 4
    for (int g = glo; g <= ghi; g++) {
        // all six loads independent -> issue back-to-back, pipeline across iters
        const int    hs = g_head_seg[g];
        const int    ts = g_tail_seg[g];
        const float4 hv = *reinterpret_cast<const float4*>(g_head_num + (long long)g * HD + lane * 4);
        const float4 tv = *reinterpret_cast<const float4*>(g_tail_num + (long long)g * HD + lane * 4);
        const float  hd = g_head_d[g];
        const float  td = g_tail_d[g];

        const float hm = (hs == s) ? 1.0f : 0.0f;
        const float tm = (ts == s) ? 1.0f : 0.0f;

        num.x += hm * hv.x + tm * tv.x;
        num.y += hm * hv.y + tm * tv.y;
        num.z += hm * hv.z + tm * tv.z;
        num.w += hm * hv.w + tm * tv.w;
        d     += hm * hd   + tm * td;
        matches += (hs == s) + (ts == s);
    }
    if (matches == 0) {
        num = *reinterpret_cast<const float4*>(g_num_acc + (long long)s * HD + lane * 4);
        d   = g_d_acc[s];
    }
    const float inv = 1.0f / (d + 1e-16f);
    num.x *= inv; num.y *= inv; num.z *= inv; num.w *= inv;
    *outv = num;
}

extern "C" void kernel_launch(void* const* d_in, const int* in_sizes, int n_in,
                              void* d_out, int out_size)
{
    const float* x     = (const float*)d_in[0];
    // d_in[1] = edge_index (unused by the forward math)
    const int*   batch = (const int*)d_in[2];
    const float* W     = (const float*)d_in[3];
    // d_in[4] = b (zeros; cancels in the softmax)
    float* out = (float*)d_out;

    const int N = in_sizes[2];
    const int B = out_size / HD;

    gap_k1<<<GRID1, NTHREADS>>>(x, batch, W, N);
    gap_k2<<<(B + WPB - 1) / WPB, NTHREADS>>>(out, N, B);
}

// round 16
// speedup vs baseline: 1.1209x; 1.0054x over previous
#include <cuda_runtime.h>
#include <cuda_bf16.h>
#include <cstdint>

#define HD 128
#define WPB 8                       // warps per CTA
#define NTHREADS (WPB * 32)
#define GRID1 740                   // 148 SMs * 5 CTAs (regs<=48 -> 5 CTAs/SM resident)
#define NWTOT (GRID1 * WPB)         // 5920 worker warps
#define BMAX 2048                   // scratch sized for up to 2048 segments

// ---- persistent scratch (zero-initialized at module load) ----
// Invariant: for an EMPTY segment s nothing ever writes g_seg_end[s] (any run,
// any replay) so it stays 0; a NON-EMPTY segment gets g_seg_end[s]=j>=1 from
// exactly one warp. Hence g_seg_end[s]==0 <=> empty; no init kernel needed.
__device__ float g_head_num[NWTOT * HD];
__device__ float g_tail_num[NWTOT * HD];
__device__ float g_head_d[NWTOT];
__device__ float g_tail_d[NWTOT];
__device__ int   g_head_seg[NWTOT];
__device__ int   g_tail_seg[NWTOT];
__device__ float g_num_acc[BMAX * HD];   // direct-stored exclusive segments
__device__ float g_d_acc[BMAX];
__device__ int   g_seg_start[BMAX];
__device__ int   g_seg_end[BMAX];        // 0 => empty segment

// K1: each global warp g owns contiguous rows [g*RPW, min((g+1)*RPW, N)).
// Splits its range into same-segment runs; accumulates d = sum exp(s_i),
// num = sum exp(s_i)*x_i per run; flushes each run to the exclusive
// per-segment slot or the warp's head/tail partial slot. Records TRUE
// segment start/end rows (single writer each).
// The 4-row warp reduction is done JOINTLY: fold (p0,p1) and (p2,p3) at
// offset 16, fold the two results at offset 8 (-> lanes 0-7 own row0,
// 8-15 row2, 16-23 row1, 24-31 row3), then 3 butterflies finish each 8-lane
// group: 10 SHFL + 1 MUFU per 4 rows instead of 20 SHFL + 4 MUFU.
__global__ void __launch_bounds__(NTHREADS, 5)
gap_k1(const float* __restrict__ x,
       const int*   __restrict__ batch,
       const float* __restrict__ W,
       int N)
{
    const int wid  = threadIdx.x >> 5;
    const int lane = threadIdx.x & 31;
    const int g    = blockIdx.x * WPB + wid;

    const int rpw = (N + NWTOT - 1) / NWTOT;
    const long long rl = (long long)g * rpw;

    int hseg = -1, tseg = -1;

    if (rl < N) {
        const int lo = (int)rl;
        const int hi = min(lo + rpw, N);
        const float4 Wv = *reinterpret_cast<const float4*>(W + lane * 4);
        const long long col = (long long)lane * 4;
        const bool b16 = (lane & 16) != 0;
        const bool b8  = (lane & 8)  != 0;

        int i = lo;
        while (i < hi) {
            const int seg = batch[i];
            // upper_bound(seg) in (i, hi)
            int a = i + 1, b = hi;
            while (a < b) { int m = (a + b) >> 1; if (batch[m] <= seg) a = m + 1; else b = m; }
            const int j = a;

            float  d = 0.0f;
            float4 num = make_float4(0.0f, 0.0f, 0.0f, 0.0f);

            int r = i;
            // 4 consecutive rows per iter: 4 independent LDG.128, 2KB contiguous
            for (; r + 4 <= j; r += 4) {
                const float4 x0 = __ldcs(reinterpret_cast<const float4*>(x + (long long)(r    ) * HD + col));
                const float4 x1 = __ldcs(reinterpret_cast<const float4*>(x + (long long)(r + 1) * HD + col));
                const float4 x2 = __ldcs(reinterpret_cast<const float4*>(x + (long long)(r + 2) * HD + col));
                const float4 x3 = __ldcs(reinterpret_cast<const float4*>(x + (long long)(r + 3) * HD + col));

                const float p0 = x0.x * Wv.x + x0.y * Wv.y + x0.z * Wv.z + x0.w * Wv.w;
                const float p1 = x1.x * Wv.x + x1.y * Wv.y + x1.z * Wv.z + x1.w * Wv.w;
                const float p2 = x2.x * Wv.x + x2.y * Wv.y + x2.z * Wv.z + x2.w * Wv.w;
                const float p3 = x3.x * Wv.x + x3.y * Wv.y + x3.z * Wv.z + x3.w * Wv.w;

                // joint 4-row reduction (10 SHFL total)
                // fold (p0,p1) at offset 16: lanes<16 keep row0, lanes>=16 row1
                const float rA = __shfl_xor_sync(0xffffffffu, b16 ? p0 : p1, 16);
                const float cA = (b16 ? p1 : p0) + rA;
                // fold (p2,p3) at offset 16
                const float rB = __shfl_xor_sync(0xffffffffu, b16 ? p2 : p3, 16);
                const float cB = (b16 ? p3 : p2) + rB;
                // fold (cA,cB) at offset 8: groups of 8 -> rows 0,2,1,3
                const float rC = __shfl_xor_sync(0xffffffffu, b8 ? cA : cB, 8);
                float cC = (b8 ? cB : cA) + rC;
                // finish within each 8-lane group
                cC += __shfl_xor_sync(0xffffffffu, cC, 4);
                cC += __shfl_xor_sync(0xffffffffu, cC, 2);
                cC += __shfl_xor_sync(0xffffffffu, cC, 1);

                // one exp per lane (each lane holds its group's row score)
                const float e = __expf(cC);
                // redistribute: lanes 0-7 hold e(row0), 8-15 e(row2),
                //               16-23 e(row1), 24-31 e(row3)
                const float e0 = __shfl_sync(0xffffffffu, e, 0);
                const float e2 = __shfl_sync(0xffffffffu, e, 8);
                const float e1 = __shfl_sync(0xffffffffu, e, 16);
                const float e3 = __shfl_sync(0xffffffffu, e, 24);

                d += (e0 + e1) + (e2 + e3);
                num.x += e0 * x0.x + e1 * x1.x + e2 * x2.x + e3 * x3.x;
                num.y += e0 * x0.y + e1 * x1.y + e2 * x2.y + e3 * x3.y;
                num.z += e0 * x0.z + e1 * x1.z + e2 * x2.z + e3 * x3.z;
                num.w += e0 * x0.w + e1 * x1.w + e2 * x2.w + e3 * x3.w;
            }
            for (; r < j; r++) {
                const float4 xv = __ldcs(reinterpret_cast<const float4*>(x + (long long)r * HD + col));
                float p = xv.x * Wv.x + xv.y * Wv.y + xv.z * Wv.z + xv.w * Wv.w;
                #pragma unroll
                for (int o = 16; o > 0; o >>= 1) p += __shfl_xor_sync(0xffffffffu, p, o);
                const float e = __expf(p);
                d += e;
                num.x += e * xv.x; num.y += e * xv.y; num.z += e * xv.z; num.w += e * xv.w;
            }

            const bool sb = (i == lo) && (lo > 0) && (batch[lo - 1] == seg);   // continues before
            const bool ea = (j == hi) && (hi < N) && (batch[hi] == seg);       // continues after

            if (lane == 0) {
                if (!sb) g_seg_start[seg] = i;   // true segment start (unique writer)
                if (!ea) g_seg_end[seg]   = j;   // true segment end   (unique writer, j >= 1)
            }

            if (!sb && !ea) {
                // exclusive segment: this warp is the sole contributor
                *reinterpret_cast<float4*>(g_num_acc + (long long)seg * HD + lane * 4) = num;
                if (lane == 0) g_d_acc[seg] = d;
            } else if (sb) {
                hseg = seg;
                *reinterpret_cast<float4*>(g_head_num + (long long)g * HD + lane * 4) = num;
                if (lane == 0) g_head_d[g] = d;
            } else {
                tseg = seg;
                *reinterpret_cast<float4*>(g_tail_num + (long long)g * HD + lane * 4) = num;
                if (lane == 0) g_tail_d[g] = d;
            }
            i = j;
        }
    }
    if (lane == 0) { g_head_seg[g] = hseg; g_tail_seg[g] = tseg; }
}

// K2: one WARP per segment (8 segments per 256-thread CTA, grid B/8).
// Lane l owns columns [4l, 4l+4) as a float4. The scan conditions are
// lane-uniform; scratch rows are 512B and each lane's float4 load coalesces.
// Empty segment: g_seg_end[s] == 0 (never written; zero-init) -> zeros.
__global__ void __launch_bounds__(NTHREADS)
gap_k2(float* __restrict__ out, int N, int B)
{
    const int wid  = threadIdx.x >> 5;
    const int lane = threadIdx.x & 31;
    const int s    = blockIdx.x * WPB + wid;
    if (s >= B) return;

    float4* outv = reinterpret_cast<float4*>(out + (long long)s * HD + lane * 4);

    const int se = g_seg_end[s];
    if (se == 0) { *outv = make_float4(0.0f, 0.0f, 0.0f, 0.0f); return; }
    const int ss = g_seg_start[s];

    const int rpw = (N + NWTOT - 1) / NWTOT;
    const int glo = ss / rpw;
    const int ghi = (se - 1) / rpw;

    float4 num = make_float4(0.0f, 0.0f, 0.0f, 0.0f);
    float  d = 0.0f;
    int matches = 0;
    for (int g = glo; g <= ghi; g++) {
        if (g_head_seg[g] == s) {
            const float4 v = *reinterpret_cast<const float4*>(g_head_num + (long long)g * HD + lane * 4);
            num.x += v.x; num.y += v.y; num.z += v.z; num.w += v.w;
            d += g_head_d[g]; matches++;
        }
        if (g_tail_seg[g] == s) {
            const float4 v = *reinterpret_cast<const float4*>(g_tail_num + (long long)g * HD + lane * 4);
            num.x += v.x; num.y += v.y; num.z += v.z; num.w += v.w;
            d += g_tail_d[g]; matches++;
        }
    }
    if (matches == 0) {
        num = *reinterpret_cast<const float4*>(g_num_acc + (long long)s * HD + lane * 4);
        d   = g_d_acc[s];
    }
    const float inv = 1.0f / (d + 1e-16f);
    num.x *= inv; num.y *= inv; num.z *= inv; num.w *= inv;
    *outv = num;
}

extern "C" void kernel_launch(void* const* d_in, const int* in_sizes, int n_in,
                              void* d_out, int out_size)
{
    const float* x     = (const float*)d_in[0];
    // d_in[1] = edge_index (unused by the forward math)
    const int*   batch = (const int*)d_in[2];
    const float* W     = (const float*)d_in[3];
    // d_in[4] = b (zeros; cancels in the softmax)
    float* out = (float*)d_out;

    const int N = in_sizes[2];
    const int B = out_size / HD;

    gap_k1<<<GRID1, NTHREADS>>>(x, batch, W, N);
    gap_k2<<<(B + WPB - 1) / WPB, NTHREADS>>>(out, N, B);
}